// round 15
// baseline (speedup 1.0000x reference)
#include <cuda_runtime.h>

#define NN    1024
#define KNB   16
#define CS    256
#define CZ    128
#define CG    16
#define NRBF  64
#define NPAIR 256    // KNB*KNB
#define NUPAIR 136   // unique pairs j<=k

typedef unsigned long long ull;

// Scratch for precomputed node projections nl = nf@Wl+bl, nr = nf@Wr+br
__device__ float g_nl[NN * CG];
__device__ float g_nr[NN * CG];

struct alignas(16) Smem {
    float z[KNB * CZ];          // layernormed knn edge feats      8 KB
    float e2[KNB * CZ];         // sigmoid(zWeg+beg)*(zWep+bep)    8 KB
    float upd[KNB * CZ];        // triangle update accumulator     8 KB
    float aT[CG][KNB];          // nl[src] transposed              1 KB
    float bT[CG][KNB];          // nr[src] transposed              1 KB
    union {
        float rbfT[NRBF * NUPAIR];  // rbf[r][upair]              34 KB
        float T[KNB * CG * 32];     // T[(j*16+g2)*32+lane]       32 KB
    } u;
    float df[NPAIR * CZ];       // masked df[(j*16+k)*128 + c]   128 KB
    float tpos[KNB][4];
    float maskf[KNB];
    int   srcIdx[KNB];
    int   pj[NUPAIR];
    int   pk[NUPAIR];
};

__device__ __forceinline__ ull pk2(float x, float y) {
    ull r; asm("mov.b64 %0, {%1, %2};" : "=l"(r) : "f"(x), "f"(y)); return r;
}
__device__ __forceinline__ void upk2(float& x, float& y, ull v) {
    asm("mov.b64 {%0, %1}, %2;" : "=f"(x), "=f"(y) : "l"(v));
}
__device__ __forceinline__ ull ffma2(ull a, ull b, ull c) {
    ull d; asm("fma.rn.f32x2 %0, %1, %2, %3;" : "=l"(d) : "l"(a), "l"(b), "l"(c)); return d;
}

__device__ __forceinline__ float red16(float v) {
    v += __shfl_xor_sync(0xffffffffu, v, 8, 16);
    v += __shfl_xor_sync(0xffffffffu, v, 4, 16);
    v += __shfl_xor_sync(0xffffffffu, v, 2, 16);
    v += __shfl_xor_sync(0xffffffffu, v, 1, 16);
    return v;
}

__device__ __forceinline__ float sigmoidf_(float x) {
    return 1.0f / (1.0f + __expf(-x));
}

// ---------------------------------------------------------------------------
// Kernel 1: nl/nr = node_features @ {Wl,Wr} + {bl,br}   (1024x256 @ 256x16)
// ---------------------------------------------------------------------------
__global__ void nlnr_kernel(const float* __restrict__ nf,
                            const float* __restrict__ Wl, const float* __restrict__ bl,
                            const float* __restrict__ Wr, const float* __restrict__ br) {
    int idx = blockIdx.x * blockDim.x + threadIdx.x;   // 16384 = NN*CG
    int node = idx >> 4, g = idx & 15;
    const float* row = nf + node * CS;
    float al = bl[g], ar = br[g];
#pragma unroll 4
    for (int s = 0; s < CS; s++) {
        float v = __ldg(row + s);
        al = fmaf(v, Wl[s * CG + g], al);
        ar = fmaf(v, Wr[s * CG + g], ar);
    }
    g_nl[idx] = al;
    g_nr[idx] = ar;
}

// ---------------------------------------------------------------------------
// Kernel 2: fully fused triangle multiplicative update, one CTA per node
// ---------------------------------------------------------------------------
__global__ void __launch_bounds__(256, 1)
tmu_kernel(const float* __restrict__ ef,    const float* __restrict__ trans,
           const float* __restrict__ ln_g,  const float* __restrict__ ln_b,
           const float* __restrict__ Wep,   const float* __restrict__ bep,
           const float* __restrict__ Weg,   const float* __restrict__ beg,
           const float* __restrict__ Wdg,   const float* __restrict__ bdg,
           const float* __restrict__ Wdp,   const float* __restrict__ bdp,
           const float* __restrict__ lno_g, const float* __restrict__ lno_b,
           const float* __restrict__ Wout,  const float* __restrict__ bout,
           const float* __restrict__ Wog,   const float* __restrict__ bog,
           const int* __restrict__ eidx,          // int32 words; dtype probed
           const unsigned char* __restrict__ rmask, // element stride probed
           float* __restrict__ out) {
    extern __shared__ unsigned char smraw[];
    Smem& sm = *reinterpret_cast<Smem*>(smraw);

    const int i    = blockIdx.x;
    const int tid  = threadIdx.x;
    const int lane = tid & 31;
    const int w    = tid >> 5;

    // --- init: src indices, mask, translations, unique-pair table ---
    if (tid < KNB) {
        // Probe edge_index storage width. Values lie in [0,1024). If stored as
        // int64 (LE), every odd 32-bit word is a zero high-half. If stored as
        // int32, odd words are random src indices (all-zero prob ~2^-160).
        int odd_or = 0;
#pragma unroll
        for (int q = 1; q < 32; q += 2) odd_or |= __ldg(eidx + q);
        int si;
        if (odd_or == 0) si = __ldg(eidx + 2 * (i * KNB + tid));  // int64 storage
        else             si = __ldg(eidx + (i * KNB + tid));      // int32 storage
        sm.srcIdx[tid] = si;

        // Probe res_mask element stride. All-true mask of width w is bytes
        // [1,0,...,0] repeated: bytes 1,2,3,5,6,7 nonzero <=> 1-byte bool;
        // else byte 4/12/20 nonzero <=> 4-byte int32; else 8-byte int64.
        int mb = rmask[1] | rmask[2] | rmask[3] | rmask[5] | rmask[6] | rmask[7];
        int m4 = rmask[4] | rmask[12] | rmask[20];
        int ms = mb ? 1 : (m4 ? 4 : 8);
        float mi = rmask[(size_t)i * ms] ? 1.0f : 0.0f;
        sm.maskf[tid] = (rmask[(size_t)si * ms] ? 1.0f : 0.0f) * mi;

        sm.tpos[tid][0] = trans[si * 3 + 0];
        sm.tpos[tid][1] = trans[si * 3 + 1];
        sm.tpos[tid][2] = trans[si * 3 + 2];
    }
    if (tid < NUPAIR) {
        int rem = tid, j = 0;
        while (rem >= KNB - j) { rem -= KNB - j; j++; }
        sm.pj[tid] = j;
        sm.pk[tid] = j + rem;
    }
    __syncthreads();

    // --- z = LayerNorm(edge feats) --- (16 threads per row, 8 ch each)
    {
        int j = tid >> 4, l = tid & 15;
        const float* er = ef + ((size_t)(i * KNB + j)) * CZ + l * 8;
        float4 v0 = *(const float4*)er;
        float4 v1 = *(const float4*)(er + 4);
        float x[8] = {v0.x, v0.y, v0.z, v0.w, v1.x, v1.y, v1.z, v1.w};
        float s = 0.0f;
#pragma unroll
        for (int q = 0; q < 8; q++) s += x[q];
        s = red16(s);
        float m = s * (1.0f / CZ);
        float ss = 0.0f;
#pragma unroll
        for (int q = 0; q < 8; q++) { float d = x[q] - m; ss = fmaf(d, d, ss); }
        ss = red16(ss);
        float rs = rsqrtf(ss * (1.0f / CZ) + 1e-5f);
        int cb = l * 8;
#pragma unroll
        for (int q = 0; q < 8; q++)
            sm.z[j * CZ + cb + q] = fmaf((x[q] - m) * rs, ln_g[cb + q], ln_b[cb + q]);
    }

    // --- gather aT = nl[src]^T, bT = nr[src]^T ---
    {
        int j = tid >> 4, g = tid & 15;
        int s = sm.srcIdx[j];
        sm.aT[g][j] = g_nl[s * CG + g];
        sm.bT[g][j] = g_nr[s * CG + g];
    }

    // --- rbf table over unique pairs: rbfT[r][p] ---
    if (tid < NUPAIR) {
        int j = sm.pj[tid], k = sm.pk[tid];
        float dx = sm.tpos[j][0] - sm.tpos[k][0] + 1e-8f;
        float dy = sm.tpos[j][1] - sm.tpos[k][1] + 1e-8f;
        float dz = sm.tpos[j][2] - sm.tpos[k][2] + 1e-8f;
        float d = sqrtf(fmaf(dx, dx, fmaf(dy, dy, dz * dz)));
        const float stepm = 20.0f / 63.0f;     // linspace(0,20,64) step
        const float invs  = 64.0f / 20.0f;     // 1/sigma, sigma = 20/64
#pragma unroll 8
        for (int r = 0; r < NRBF; r++) {
            float uu = (d - (float)r * stepm) * invs;
            sm.u.rbfT[r * NUPAIR + tid] = __expf(-uu * uu);
        }
    }
    __syncthreads();

    // --- df = (rbf @ Wdp + bdp) * pair mask, all 128 channels, unique + mirror ---
    {
        const int c = tid & (CZ - 1);
        const int h = tid >> 7;            // which half of the 136 pairs
        ull wdp2[NRBF];
#pragma unroll
        for (int r = 0; r < NRBF; r++) { float v = Wdp[r * CZ + c]; wdp2[r] = pk2(v, v); }
        const float bdpc = bdp[c];
        const ull bdp2 = pk2(bdpc, bdpc);
#pragma unroll 1
        for (int q = 0; q < 17; q++) {
            int p0 = h * 68 + q * 4;
            ull a01 = bdp2, a23 = bdp2;
#pragma unroll
            for (int r = 0; r < NRBF; r++) {
                ulonglong2 rb = *(const ulonglong2*)&sm.u.rbfT[r * NUPAIR + p0];
                a01 = ffma2(rb.x, wdp2[r], a01);
                a23 = ffma2(rb.y, wdp2[r], a23);
            }
            float d0, d1, d2, d3;
            upk2(d0, d1, a01); upk2(d2, d3, a23);
            float dv[4] = {d0, d1, d2, d3};
#pragma unroll
            for (int t = 0; t < 4; t++) {
                int p = p0 + t;
                int j = sm.pj[p], k = sm.pk[p];
                float val = dv[t] * (sm.maskf[j] * sm.maskf[k]);  // fold pair mask
                sm.df[(j * KNB + k) * CZ + c] = val;
                sm.df[(k * KNB + j) * CZ + c] = val;              // symmetric mirror
            }
        }
    }

    // --- e2 = sigmoid(z@Weg+beg) * (z@Wep+bep) ---
    {
        int c  = tid & (CZ - 1);
        int jh = tid >> 7;   // 0 or 1 -> rows jh*8 .. jh*8+7
        float ag[8], ap[8];
        float bgc = beg[c], bpc = bep[c];
#pragma unroll
        for (int q = 0; q < 8; q++) { ag[q] = bgc; ap[q] = bpc; }
        for (int s = 0; s < CZ; s += 4) {
            float wg0 = Weg[(s + 0) * CZ + c], wg1 = Weg[(s + 1) * CZ + c];
            float wg2 = Weg[(s + 2) * CZ + c], wg3 = Weg[(s + 3) * CZ + c];
            float wp0 = Wep[(s + 0) * CZ + c], wp1 = Wep[(s + 1) * CZ + c];
            float wp2 = Wep[(s + 2) * CZ + c], wp3 = Wep[(s + 3) * CZ + c];
#pragma unroll
            for (int jj = 0; jj < 8; jj++) {
                const float4 z4 = *(const float4*)&sm.z[(jh * 8 + jj) * CZ + s];
                ag[jj] = fmaf(z4.x, wg0, fmaf(z4.y, wg1, fmaf(z4.z, wg2, fmaf(z4.w, wg3, ag[jj]))));
                ap[jj] = fmaf(z4.x, wp0, fmaf(z4.y, wp1, fmaf(z4.z, wp2, fmaf(z4.w, wp3, ap[jj]))));
            }
        }
#pragma unroll
        for (int jj = 0; jj < 8; jj++)
            sm.e2[(jh * 8 + jj) * CZ + c] = sigmoidf_(ag[jj]) * ap[jj];
    }
    __syncthreads();

    // --- main loop: 4 channel chunks of 32; factorized gate + contraction ---
    for (int c0 = 0; c0 < CZ; c0 += 32) {
        const int c = c0 + lane;
        const float bdgc = bdg[c];

        // T build (packed over j-pairs): T[j][g2][lane] = sum_g1 aT[g1][j]*Wdg[(g1*16+g2)*CZ+c]
#pragma unroll
        for (int gi = 0; gi < 2; gi++) {
            int g2 = w + gi * 8;
            ull wr2[CG];
#pragma unroll
            for (int g1 = 0; g1 < CG; g1++) {
                float v = Wdg[(g1 * CG + g2) * CZ + c];
                wr2[g1] = pk2(v, v);
            }
#pragma unroll
            for (int jp = 0; jp < 8; jp++) {
                ull t2 = 0ull;   // (0.0f, 0.0f)
#pragma unroll
                for (int g1 = 0; g1 < CG; g1++) {
                    ull a2 = *(const ull*)&sm.aT[g1][jp * 2];
                    t2 = ffma2(a2, wr2[g1], t2);
                }
                float tx, ty; upk2(tx, ty, t2);
                sm.u.T[((jp * 2 + 0) * CG + g2) * 32 + lane] = tx;
                sm.u.T[((jp * 2 + 1) * CG + g2) * 32 + lane] = ty;
            }
        }
        __syncthreads();

        // pair phase: warp w owns rows j = w and w+8; lane owns channel c
#pragma unroll
        for (int ji = 0; ji < 2; ji++) {
            int j = w + ji * 8;
            float treg[CG];
#pragma unroll
            for (int g2 = 0; g2 < CG; g2++) treg[g2] = sm.u.T[(j * CG + g2) * 32 + lane];

            // gate[j,k] = bdg + sum_g2 T[j,g2]*bT[g2][k], packed over k-pairs
            ull bdg2 = pk2(bdgc, bdgc);
            ull ga[8];
#pragma unroll
            for (int q = 0; q < 8; q++) ga[q] = bdg2;
#pragma unroll
            for (int g2 = 0; g2 < CG; g2++) {
                ull tv2 = pk2(treg[g2], treg[g2]);
                const ulonglong2* bp = (const ulonglong2*)&sm.bT[g2][0];
                ulonglong2 q0 = bp[0], q1 = bp[1], q2 = bp[2], q3 = bp[3];
                ga[0] = ffma2(tv2, q0.x, ga[0]); ga[1] = ffma2(tv2, q0.y, ga[1]);
                ga[2] = ffma2(tv2, q1.x, ga[2]); ga[3] = ffma2(tv2, q1.y, ga[3]);
                ga[4] = ffma2(tv2, q2.x, ga[4]); ga[5] = ffma2(tv2, q2.y, ga[5]);
                ga[6] = ffma2(tv2, q3.x, ga[6]); ga[7] = ffma2(tv2, q3.y, ga[7]);
            }

            float acc = 0.0f;
#pragma unroll
            for (int kk = 0; kk < 8; kk++) {
                float gA, gB; upk2(gA, gB, ga[kk]);
                int k = kk * 2;
                // df already carries the pair mask
                float e3a = sigmoidf_(gA) * sm.df[(j * KNB + k) * CZ + c];
                float e3b = sigmoidf_(gB) * sm.df[(j * KNB + k + 1) * CZ + c];
                acc = fmaf(e3a, sm.e2[k * CZ + c], acc);
                acc = fmaf(e3b, sm.e2[(k + 1) * CZ + c], acc);
            }
            sm.upd[j * CZ + c] = acc;
        }
        __syncthreads();
    }

    // --- LN(upd) in place (lno params) ---
    {
        int j = tid >> 4, l = tid & 15;
        float* up = &sm.upd[j * CZ + l * 8];
        float4 v0 = *(float4*)up;
        float4 v1 = *(float4*)(up + 4);
        float x[8] = {v0.x, v0.y, v0.z, v0.w, v1.x, v1.y, v1.z, v1.w};
        float s = 0.0f;
#pragma unroll
        for (int q = 0; q < 8; q++) s += x[q];
        s = red16(s);
        float m = s * (1.0f / CZ);
        float ss = 0.0f;
#pragma unroll
        for (int q = 0; q < 8; q++) { float d = x[q] - m; ss = fmaf(d, d, ss); }
        ss = red16(ss);
        float rs = rsqrtf(ss * (1.0f / CZ) + 1e-5f);
        int cb = l * 8;
#pragma unroll
        for (int q = 0; q < 8; q++)
            up[q] = fmaf((x[q] - m) * rs, lno_g[cb + q], lno_b[cb + q]);
    }
    __syncthreads();

    // --- final: (LN(upd)@Wout+bout) * sigmoid(z@Wog+bog) * mask -> out ---
    {
        int c  = tid & (CZ - 1);
        int jh = tid >> 7;
        float ao[8], ag[8];
        float boc = bout[c], bgc = bog[c];
#pragma unroll
        for (int q = 0; q < 8; q++) { ao[q] = boc; ag[q] = bgc; }
        for (int s = 0; s < CZ; s += 4) {
            float wo0 = Wout[(s + 0) * CZ + c], wo1 = Wout[(s + 1) * CZ + c];
            float wo2 = Wout[(s + 2) * CZ + c], wo3 = Wout[(s + 3) * CZ + c];
            float wg0 = Wog[(s + 0) * CZ + c],  wg1 = Wog[(s + 1) * CZ + c];
            float wg2 = Wog[(s + 2) * CZ + c],  wg3 = Wog[(s + 3) * CZ + c];
#pragma unroll
            for (int jj = 0; jj < 8; jj++) {
                const float4 u4 = *(const float4*)&sm.upd[(jh * 8 + jj) * CZ + s];
                const float4 z4 = *(const float4*)&sm.z[(jh * 8 + jj) * CZ + s];
                ao[jj] = fmaf(u4.x, wo0, fmaf(u4.y, wo1, fmaf(u4.z, wo2, fmaf(u4.w, wo3, ao[jj]))));
                ag[jj] = fmaf(z4.x, wg0, fmaf(z4.y, wg1, fmaf(z4.z, wg2, fmaf(z4.w, wg3, ag[jj]))));
            }
        }
#pragma unroll
        for (int jj = 0; jj < 8; jj++) {
            int j = jh * 8 + jj;
            float val = ao[jj] * sigmoidf_(ag[jj]) * sm.maskf[j];
            out[((size_t)(i * KNB + j)) * CZ + c] = val;
        }
    }
}

// ---------------------------------------------------------------------------
extern "C" void kernel_launch(void* const* d_in, const int* in_sizes, int n_in,
                              void* d_out, int out_size) {
    const float*     nf    = (const float*)d_in[0];
    const float*     trans = (const float*)d_in[1];
    const float*     ef    = (const float*)d_in[2];
    const float*     ln_g  = (const float*)d_in[3];
    const float*     ln_b  = (const float*)d_in[4];
    const float*     Wl    = (const float*)d_in[5];
    const float*     bl    = (const float*)d_in[6];
    const float*     Wr    = (const float*)d_in[7];
    const float*     br    = (const float*)d_in[8];
    const float*     Wep   = (const float*)d_in[9];
    const float*     bep   = (const float*)d_in[10];
    const float*     Weg   = (const float*)d_in[11];
    const float*     beg   = (const float*)d_in[12];
    const float*     Wdg   = (const float*)d_in[13];
    const float*     bdg   = (const float*)d_in[14];
    const float*     Wdp   = (const float*)d_in[15];
    const float*     bdp   = (const float*)d_in[16];
    const float*     lno_g = (const float*)d_in[17];
    const float*     lno_b = (const float*)d_in[18];
    const float*     Wout  = (const float*)d_in[19];
    const float*     bout  = (const float*)d_in[20];
    const float*     Wog   = (const float*)d_in[21];
    const float*     bog   = (const float*)d_in[22];
    const int*       eidx  = (const int*)d_in[23];   // width auto-detected
    const unsigned char* rmask = (const unsigned char*)d_in[25]; // stride auto-detected
    float* out = (float*)d_out;

    cudaFuncSetAttribute(tmu_kernel, cudaFuncAttributeMaxDynamicSharedMemorySize,
                         (int)sizeof(Smem));

    nlnr_kernel<<<(NN * CG) / 256, 256>>>(nf, Wl, bl, Wr, br);

    tmu_kernel<<<NN, 256, sizeof(Smem)>>>(ef, trans, ln_g, ln_b,
                                          Wep, bep, Weg, beg, Wdg, bdg, Wdp, bdp,
                                          lno_g, lno_b, Wout, bout, Wog, bog,
                                          eidx, rmask, out);
}